// round 15
// baseline (speedup 1.0000x reference)
#include <cuda_runtime.h>
#include <cuda_bf16.h>
#include <math.h>
#include <stdint.h>

#define B_ 2048
#define M_ 128
#define E_ 256
#define H_ 256
#define S_ 64
#define F_ 4

#if defined(__CUDA_ARCH__) && (defined(__CUDA_ARCH_FEAT_SM103_ALL) || defined(__CUDA_ARCH_FEAT_SM103A_ALL))
#define TC_PATH 1
#else
#define TC_PATH 0
#endif

// ---------------- device scratch ----------------
__device__ float g_X0f[B_ * 512], g_X1f[B_ * 512], g_XAf[B_ * 512];
__device__ float g_W0f[1024 * 512], g_W1f[1024 * 512];
__device__ __nv_bfloat16 g_X0hi[B_ * 512], g_X0lo[B_ * 512];
__device__ __nv_bfloat16 g_X1hi[B_ * 512], g_X1lo[B_ * 512];
__device__ __nv_bfloat16 g_XAhi[B_ * 512], g_XAlo[B_ * 512];
__device__ __nv_bfloat16 g_W0hi[1024 * 512], g_W0lo[1024 * 512];
__device__ __nv_bfloat16 g_W1hi[1024 * 512], g_W1lo[1024 * 512];
__device__ __nv_bfloat16 g_WAhi[256 * 512], g_WAlo[256 * 512];
__device__ float g_bsum0[1024], g_bsum1[1024];   // permuted combined biases
__device__ float g_O1[B_ * 256];
__device__ float g_ATT[B_ * 256];

// ---------------- helpers ----------------
__device__ __forceinline__ uint32_t smem_u32(const void* p) {
    uint32_t a;
    asm("{ .reg .u64 t; cvta.to.shared.u64 t, %1; cvt.u32.u64 %0, t; }" : "=r"(a) : "l"(p));
    return a;
}
__device__ __forceinline__ void bsplit(float x, __nv_bfloat16* hi, __nv_bfloat16* lo) {
    __nv_bfloat16 h = __float2bfloat16(x);
    *hi = h;
    *lo = __float2bfloat16(x - __bfloat162float(h));
}
__device__ __forceinline__ float sigf(float x) { return 1.f / (1.f + __expf(-x)); }

#if TC_PATH
__device__ __forceinline__ uint32_t elect1() {
    uint32_t p;
    asm volatile("{\n\t.reg .pred p;\n\telect.sync _|p, 0xFFFFFFFF;\n\tselp.b32 %0,1,0,p;\n\t}" : "=r"(p));
    return p;
}
__device__ __forceinline__ void mbar_wait(uint32_t addr, uint32_t parity) {
    asm volatile(
        "{\n\t.reg .pred P;\n\t"
        "WL_%=:\n\t"
        "mbarrier.try_wait.parity.acquire.cta.shared::cta.b64 P, [%0], %1, 0x989680;\n\t"
        "@P bra.uni WD_%=;\n\t"
        "bra.uni WL_%=;\n\t"
        "WD_%=:\n\t}"
        :: "r"(addr), "r"(parity) : "memory");
}
__device__ __forceinline__ void mma_bf16_ss(uint32_t d, uint64_t da, uint64_t db,
                                            uint32_t idesc, uint32_t en) {
    asm volatile(
        "{\n\t.reg .pred p;\n\tsetp.ne.u32 p, %4, 0;\n\t"
        "tcgen05.mma.cta_group::1.kind::f16 [%0], %1, %2, %3, {%5,%5,%5,%5}, p;\n\t}"
        :: "r"(d), "l"(da), "l"(db), "r"(idesc), "r"(en), "r"(0u) : "memory");
}
__device__ __forceinline__ uint64_t mk_desc(uint32_t addr) {
    const uint64_t base = (uint64_t(2) << 61) | (uint64_t(1) << 46) |
                          (uint64_t(64) << 32) | (uint64_t(1) << 16);
    return base | ((uint64_t)(addr >> 4) & 0x3FFF);
}
#define TCLD32(r, a)                                                        \
    asm volatile(                                                           \
        "tcgen05.ld.sync.aligned.32x32b.x32.b32 "                           \
        "{%0, %1, %2, %3, %4, %5, %6, %7, "                                 \
        " %8, %9, %10, %11, %12, %13, %14, %15, "                           \
        " %16, %17, %18, %19, %20, %21, %22, %23, "                         \
        " %24, %25, %26, %27, %28, %29, %30, %31}, [%32];"                  \
        : "=r"((r)[0]), "=r"((r)[1]), "=r"((r)[2]), "=r"((r)[3]),           \
          "=r"((r)[4]), "=r"((r)[5]), "=r"((r)[6]), "=r"((r)[7]),           \
          "=r"((r)[8]), "=r"((r)[9]), "=r"((r)[10]), "=r"((r)[11]),         \
          "=r"((r)[12]), "=r"((r)[13]), "=r"((r)[14]), "=r"((r)[15]),       \
          "=r"((r)[16]), "=r"((r)[17]), "=r"((r)[18]), "=r"((r)[19]),       \
          "=r"((r)[20]), "=r"((r)[21]), "=r"((r)[22]), "=r"((r)[23]),       \
          "=r"((r)[24]), "=r"((r)[25]), "=r"((r)[26]), "=r"((r)[27]),       \
          "=r"((r)[28]), "=r"((r)[29]), "=r"((r)[30]), "=r"((r)[31])        \
        : "r"(a))
#endif  // TC_PATH

// ---------------- weight conversion (gate-interleaved permutation) ----------------
// original LSTM row n = g*256 + j (g: 0=i,1=f,2=g,3=o)  ->  permuted row n' = j*4 + g
__global__ __launch_bounds__(256)
void convw_kernel(const float* __restrict__ Wih0, const float* __restrict__ Whh0,
                  const float* __restrict__ bih0, const float* __restrict__ bhh0,
                  const float* __restrict__ Wih1, const float* __restrict__ Whh1,
                  const float* __restrict__ bih1, const float* __restrict__ bhh1,
                  const float* __restrict__ Watt) {
    int n = blockIdx.x, t = threadIdx.x;
#pragma unroll
    for (int kk = 0; kk < 2; kk++) {
        int k = t + kk * 256;
        if (n < 1024) {
            int np = (n & 255) * 4 + (n >> 8);
            float v = (k < 256) ? Wih0[n * 256 + k] : Whh0[n * 256 + k - 256];
#if !TC_PATH
            g_W0f[np * 512 + k] = v;
#endif
            bsplit(v, &g_W0hi[np * 512 + k], &g_W0lo[np * 512 + k]);
            if (t == 0 && kk == 0) g_bsum0[np] = bih0[n] + bhh0[n];
        } else if (n < 2048) {
            int m = n - 1024;
            int np = (m & 255) * 4 + (m >> 8);
            float v = (k < 256) ? Wih1[m * 256 + k] : Whh1[m * 256 + k - 256];
#if !TC_PATH
            g_W1f[np * 512 + k] = v;
#endif
            bsplit(v, &g_W1hi[np * 512 + k], &g_W1lo[np * 512 + k]);
            if (t == 0 && kk == 0) g_bsum1[np] = bih1[m] + bhh1[m];
        } else {
            int m = n - 2048;
            float v = Watt[m * 512 + k];
            bsplit(v, &g_WAhi[m * 512 + k], &g_WAlo[m * 512 + k]);
        }
    }
}

// ---------------- gather (also pre-fills X1's h1 half) ----------------
__global__ void gather0_kernel(const float* __restrict__ memory,
                               const float* __restrict__ h0,
                               const float* __restrict__ h1,
                               const int* __restrict__ read_ind) {
    int b = blockIdx.x, t = threadIdx.x;
    int ri = read_ind[b];
    float x = memory[((long)b * M_ + ri) * E_ + t];
    float h = h0[b * H_ + t];
    float h1v = h1[b * H_ + t];
#if !TC_PATH
    g_X0f[b * 512 + t] = x;
    g_X0f[b * 512 + 256 + t] = h;
    g_X1f[b * 512 + 256 + t] = h1v;
#endif
    bsplit(x, &g_X0hi[b * 512 + t], &g_X0lo[b * 512 + t]);
    bsplit(h, &g_X0hi[b * 512 + 256 + t], &g_X0lo[b * 512 + 256 + t]);
    bsplit(h1v, &g_X1hi[b * 512 + 256 + t], &g_X1lo[b * 512 + 256 + t]);
}

// ---------------- unified GEMM + fused LSTM-cell epilogue ----------------
// mode 0: C store with tanh (attention GEMM)
// mode 1: layer-0 cell epilogue  (needs bsum, cprev; outputs outH=h0n, outC=c0n, X1 splits)
// mode 2: layer-1 cell epilogue  (needs bsum, cprev, hstage=h0n; outputs h1n, c1n, O1, XA splits)
#define TSZ 16384
#define GEMM_DYN (1024 + 8 * TSZ)

__global__ __launch_bounds__(256)
void gemm_uni(const float* __restrict__ Af,
              const __nv_bfloat16* __restrict__ Ahi, const __nv_bfloat16* __restrict__ Alo,
              const float* __restrict__ Bf,
              const __nv_bfloat16* __restrict__ Bhi, const __nv_bfloat16* __restrict__ Blo,
              float* __restrict__ C, int ldc, int mode,
              const float* __restrict__ bsum,
              const float* __restrict__ cprev,
              const float* __restrict__ hstage,
              float* __restrict__ outH, float* __restrict__ outC) {
    extern __shared__ char dynraw[];
#if TC_PATH
    __shared__ uint32_t s_tmem[1];
    __shared__ __align__(8) unsigned long long s_mbar[2];
    __shared__ float s_bias[128];

    int tid = threadIdx.x, wid = tid >> 5, lane = tid & 31;
    uint32_t dynb = smem_u32(dynraw);
    uint32_t tiles_a = (dynb + 1023u) & ~1023u;
    char* tiles = dynraw + (tiles_a - dynb);
    int br = blockIdx.x * 128, bc = blockIdx.y * 128;
    uint32_t mbar0 = smem_u32(&s_mbar[0]);
    const uint32_t IDESC = (1u << 4) | (1u << 7) | (1u << 10) | (16u << 17) | (8u << 24);

    if (wid == 0) {
        asm volatile("tcgen05.alloc.cta_group::1.sync.aligned.shared::cta.b32 [%0], %1;"
                     :: "r"(smem_u32(s_tmem)), "r"(128u) : "memory");
    }
    if (tid == 0) {
        asm volatile("mbarrier.init.shared.b64 [%0], 1;" :: "r"(mbar0) : "memory");
        asm volatile("mbarrier.init.shared.b64 [%0], 1;" :: "r"(mbar0 + 8) : "memory");
    }
    __syncthreads();
    uint32_t tmem;
    asm volatile("ld.shared.b32 %0, [%1];" : "=r"(tmem) : "r"(smem_u32(s_tmem)));

    const __nv_bfloat16* srcs[4] = {Ahi, Alo, Bhi, Blo};
    int rowbases[4] = {br, br, bc, bc};

    uint4 rg[4][4];
#define LOADC(kc)                                                                    \
    do {                                                                             \
        _Pragma("unroll") for (int t = 0; t < 4; t++) {                              \
            _Pragma("unroll") for (int i = 0; i < 4; i++) {                          \
                int id = tid + i * 256;                                              \
                int r = id >> 3, c8 = id & 7;                                        \
                rg[t][i] = *reinterpret_cast<const uint4*>(                          \
                    srcs[t] + (size_t)(rowbases[t] + r) * 512 + (size_t)(kc)*64 +    \
                    c8 * 8);                                                         \
            }                                                                        \
        }                                                                            \
    } while (0)

    LOADC(0);
    for (int kc = 0; kc < 8; kc++) {
        int buf = kc & 1;
        if (kc >= 2) mbar_wait(mbar0 + buf * 8, ((kc - 2) >> 1) & 1);
        char* tb = tiles + buf * (4 * TSZ);
#pragma unroll
        for (int t = 0; t < 4; t++) {
            char* dst = tb + t * TSZ;
#pragma unroll
            for (int i = 0; i < 4; i++) {
                int id = tid + i * 256;
                int r = id >> 3, c8 = id & 7;
                uint32_t off = (uint32_t)(r * 128 + c8 * 16);
                off ^= (off >> 3) & 0x70;
                *reinterpret_cast<uint4*>(dst + off) = rg[t][i];
            }
        }
        asm volatile("fence.proxy.async.shared::cta;" ::: "memory");
        __syncthreads();
        if (wid == 0 && elect1()) {
            uint64_t dA0 = mk_desc(smem_u32(tb));
            uint64_t dA1 = mk_desc(smem_u32(tb + TSZ));
            uint64_t dB0 = mk_desc(smem_u32(tb + 2 * TSZ));
            uint64_t dB1 = mk_desc(smem_u32(tb + 3 * TSZ));
            uint64_t pa[3] = {dA0, dA0, dA1};
            uint64_t pb[3] = {dB0, dB1, dB0};
#pragma unroll
            for (int p = 0; p < 3; p++) {
#pragma unroll
                for (int s = 0; s < 4; s++) {
                    uint32_t en = (kc == 0 && p == 0 && s == 0) ? 0u : 1u;
                    mma_bf16_ss(tmem, pa[p] + s * 2, pb[p] + s * 2, IDESC, en);
                }
            }
            asm volatile(
                "tcgen05.commit.cta_group::1.mbarrier::arrive::one.shared::cluster.b64 [%0];"
                :: "r"(mbar0 + buf * 8) : "memory");
        }
        if (kc < 7) LOADC(kc + 1);
    }
#undef LOADC
    mbar_wait(mbar0, 1);
    mbar_wait(mbar0 + 8, 1);
    asm volatile("tcgen05.fence::after_thread_sync;" ::: "memory");

    int wsub = wid & 3, grp = wid >> 2;
    int r = wsub * 32 + lane;

    if (mode == 0) {
        // ------- attention epilogue: tanh + coalesced C store -------
        float* Ce = reinterpret_cast<float*>(tiles);
#pragma unroll
        for (int j = 0; j < 2; j++) {
            int c0 = grp * 64 + j * 32;
            uint32_t dr[32];
            TCLD32(dr, tmem + c0);
            asm volatile("tcgen05.wait::ld.sync.aligned;" ::: "memory");
#pragma unroll
            for (int i = 0; i < 32; i++)
                Ce[r * 129 + c0 + i] = tanhf(__uint_as_float(dr[i]));
        }
        __syncthreads();
#pragma unroll
        for (int i = 0; i < 16; i++) {
            int id = i * 256 + tid;
            int rr = id >> 5, q = id & 31;
            float4 v;
            v.x = Ce[rr * 129 + q * 4 + 0];
            v.y = Ce[rr * 129 + q * 4 + 1];
            v.z = Ce[rr * 129 + q * 4 + 2];
            v.w = Ce[rr * 129 + q * 4 + 3];
            *reinterpret_cast<float4*>(C + (size_t)(br + rr) * ldc + bc + q * 4) = v;
        }
    } else {
        // ------- fused LSTM cell epilogue -------
        float* Pf = reinterpret_cast<float*>(tiles);
        float* Ps = Pf;              // c_prev tile [128][33]
        float* Hs = Pf + 4224;       // h0n tile (mode 2)
        float* Ho = Pf + 2 * 4224;   // h out
        float* Co = Pf + 3 * 4224;   // c out
        int bcH = bc >> 2;
        if (tid < 128) s_bias[tid] = bsum[bc + tid];
        for (int idx = tid; idx < 4096; idx += 256) {
            int row = idx >> 5, jl = idx & 31;
            Ps[row * 33 + jl] = cprev[(size_t)(br + row) * 256 + bcH + jl];
            if (mode == 2)
                Hs[row * 33 + jl] = hstage[(size_t)(br + row) * 256 + bcH + jl];
        }
        __syncthreads();
#pragma unroll
        for (int j = 0; j < 2; j++) {
            int c0 = grp * 64 + j * 32;
            uint32_t dr[32];
            TCLD32(dr, tmem + c0);
            asm volatile("tcgen05.wait::ld.sync.aligned;" ::: "memory");
#pragma unroll
            for (int u = 0; u < 8; u++) {
                int cl = c0 + 4 * u;
                int jl = cl >> 2;
                float gi = __uint_as_float(dr[4 * u + 0]) + s_bias[cl + 0];
                float gf = __uint_as_float(dr[4 * u + 1]) + s_bias[cl + 1];
                float gg = __uint_as_float(dr[4 * u + 2]) + s_bias[cl + 2];
                float go = __uint_as_float(dr[4 * u + 3]) + s_bias[cl + 3];
                float i_ = sigf(gi), f_ = sigf(gf), o_ = sigf(go), gv = tanhf(gg);
                float c = f_ * Ps[r * 33 + jl] + i_ * gv;
                float h = o_ * tanhf(c);
                Ho[r * 33 + jl] = h;
                Co[r * 33 + jl] = c;
            }
        }
        __syncthreads();
        for (int idx = tid; idx < 4096; idx += 256) {
            int row = idx >> 5, jl = idx & 31;
            int b = br + row;
            int jh = bcH + jl;
            float h = Ho[row * 33 + jl];
            float c = Co[row * 33 + jl];
            outC[(size_t)b * 256 + jh] = c;
            outH[(size_t)b * 256 + jh] = h;
            if (mode == 1) {
                bsplit(h, &g_X1hi[b * 512 + jh], &g_X1lo[b * 512 + jh]);
            } else {
                float o1 = h + Hs[row * 33 + jl];
                g_O1[b * 256 + jh] = o1;
                bsplit(o1, &g_XAhi[b * 512 + jh], &g_XAlo[b * 512 + jh]);
            }
        }
    }
    __syncthreads();
    if (wid == 0) {
        asm volatile("tcgen05.relinquish_alloc_permit.cta_group::1.sync.aligned;");
        asm volatile("tcgen05.dealloc.cta_group::1.sync.aligned.b32 %0, %1;"
                     :: "r"(tmem), "r"(128u));
    }
    (void)Af; (void)Bf;
#else
    // fp32 fallback (not selected on sm_103a hardware; compile + correctness only)
    int tid = threadIdx.x;
    int tr = tid >> 4, tc = tid & 15;
    int br = blockIdx.x * 128, bc = blockIdx.y * 128;
    float acc[8][8];
#pragma unroll
    for (int i = 0; i < 8; i++)
#pragma unroll
        for (int j = 0; j < 8; j++) acc[i][j] = 0.f;
    for (int k = 0; k < 512; k++) {
#pragma unroll
        for (int j = 0; j < 8; j++) {
            float bv = Bf[(size_t)(bc + tc * 8 + j) * 512 + k];
#pragma unroll
            for (int i = 0; i < 8; i++)
                acc[i][j] += Af[(size_t)(br + tr * 8 + i) * 512 + k] * bv;
        }
    }
#pragma unroll
    for (int i = 0; i < 8; i++) {
        int rr = br + tr * 8 + i;
        if (mode == 0) {
#pragma unroll
            for (int j = 0; j < 8; j++)
                C[(size_t)rr * ldc + bc + tc * 8 + j] = tanhf(acc[i][j]);
        } else {
#pragma unroll
            for (int q = 0; q < 2; q++) {
                int cl = tc * 8 + q * 4;
                int jh = (bc + cl) >> 2;
                float gi = acc[i][q * 4 + 0] + bsum[bc + cl + 0];
                float gf = acc[i][q * 4 + 1] + bsum[bc + cl + 1];
                float gg = acc[i][q * 4 + 2] + bsum[bc + cl + 2];
                float go = acc[i][q * 4 + 3] + bsum[bc + cl + 3];
                float i_ = sigf(gi), f_ = sigf(gf), o_ = sigf(go), gv = tanhf(gg);
                float c = f_ * cprev[(size_t)rr * 256 + jh] + i_ * gv;
                float h = o_ * tanhf(c);
                outC[(size_t)rr * 256 + jh] = c;
                outH[(size_t)rr * 256 + jh] = h;
                if (mode == 1) {
                    g_X1f[rr * 512 + jh] = h;
                    bsplit(h, &g_X1hi[rr * 512 + jh], &g_X1lo[rr * 512 + jh]);
                } else {
                    float o1 = h + hstage[(size_t)rr * 256 + jh];
                    g_O1[rr * 256 + jh] = o1;
                    g_XAf[rr * 512 + jh] = o1;
                    bsplit(o1, &g_XAhi[rr * 512 + jh], &g_XAlo[rr * 512 + jh]);
                }
            }
        }
    }
    (void)Ahi; (void)Alo; (void)Bhi; (void)Blo;
#endif
}

// ---------------- attention (cell part now lives in gemm1 epilogue) ----------------
__global__ __launch_bounds__(256)
void attn_kernel(const float* __restrict__ keys,
                 const float* __restrict__ values,
                 const float* __restrict__ qmask) {
    int b = blockIdx.x;
    int tid = threadIdx.x, warp = tid >> 5, lane = tid & 31;
    __shared__ float so1[256];
    __shared__ float sw[64];
    so1[tid] = g_O1[b * 256 + tid];
    __syncthreads();

#pragma unroll
    for (int i = 0; i < 8; i++) {
        int s = warp * 8 + i;
        const float* kp = keys + ((long)b * S_ + s) * H_;
        float acc = 0.f;
#pragma unroll
        for (int j = 0; j < 8; j++) acc += kp[lane + 32 * j] * so1[lane + 32 * j];
#pragma unroll
        for (int o = 16; o > 0; o >>= 1) acc += __shfl_xor_sync(0xFFFFFFFFu, acc, o);
        if (lane == 0)
            sw[s] = (qmask[b * S_ + s] > 0.f) ? acc : -INFINITY;
    }
    __syncthreads();
    if (warp == 0) {
        float v0 = sw[lane], v1 = sw[lane + 32];
        float mx = fmaxf(v0, v1);
#pragma unroll
        for (int o = 16; o > 0; o >>= 1) mx = fmaxf(mx, __shfl_xor_sync(0xFFFFFFFFu, mx, o));
        float e0 = __expf(v0 - mx), e1 = __expf(v1 - mx);
        float s = e0 + e1;
#pragma unroll
        for (int o = 16; o > 0; o >>= 1) s += __shfl_xor_sync(0xFFFFFFFFu, s, o);
        float inv = 1.f / s;
        sw[lane] = e0 * inv;
        sw[lane + 32] = e1 * inv;
    }
    __syncthreads();
    float acc = 0.f;
    const float* vp = values + (long)b * S_ * E_ + tid;
#pragma unroll 8
    for (int s2 = 0; s2 < S_; s2++) acc += sw[s2] * vp[s2 * E_];
#if !TC_PATH
    g_XAf[b * 512 + 256 + tid] = acc;
#endif
    bsplit(acc, &g_XAhi[b * 512 + 256 + tid], &g_XAlo[b * 512 + 256 + tid]);
}

// ---------------- fused final pass (single read of memory) ----------------
__global__ __launch_bounds__(256)
void final_kernel(const float* __restrict__ memory,
                  const float* __restrict__ of,
                  const float* __restrict__ W_of,
                  const int* __restrict__ write_ind,
                  float* __restrict__ logits,
                  float* __restrict__ memory_t) {
    int b = blockIdx.x;
    int tid = threadIdx.x, warp = tid >> 5, lane = tid & 31;
    __shared__ float sa[256];
    __shared__ float swof[4];
    sa[tid] = g_ATT[b * 256 + tid];
    if (tid < 4) swof[tid] = W_of[tid];
    __syncthreads();

    int wi_raw = write_ind[b];
    float wmask = (wi_raw >= 0) ? 1.f : 0.f;
    int wi = (wi_raw >= 0) ? wi_raw : 0;

    for (int m = warp; m < M_; m += 8) {
        const float* mp = memory + ((long)b * M_ + m) * E_;
        float* mo = memory_t + ((long)b * M_ + m) * E_;
        float addf = (m == wi) ? wmask : 0.f;
        float acc = 0.f;
#pragma unroll
        for (int h = 0; h < 2; h++) {
            int e = lane * 4 + h * 128;
            float4 mv = *reinterpret_cast<const float4*>(mp + e);
            float4 av = *reinterpret_cast<const float4*>(sa + e);
            acc += mv.x * av.x + mv.y * av.y + mv.z * av.z + mv.w * av.w;
            float4 ov;
            ov.x = mv.x + addf * av.x; ov.y = mv.y + addf * av.y;
            ov.z = mv.z + addf * av.z; ov.w = mv.w + addf * av.w;
            *reinterpret_cast<float4*>(mo + e) = ov;
        }
#pragma unroll
        for (int o = 16; o > 0; o >>= 1) acc += __shfl_xor_sync(0xFFFFFFFFu, acc, o);
        if (lane == 0) {
            const float* ofp = of + ((long)b * M_ + m) * F_;
            acc += ofp[0] * swof[0] + ofp[1] * swof[1] + ofp[2] * swof[2] + ofp[3] * swof[3];
            logits[b * M_ + m] = acc;
        }
    }
}

// ---------------- launch ----------------
extern "C" void kernel_launch(void* const* d_in, const int* in_sizes, int n_in,
                              void* d_out, int out_size) {
    const float* memory = (const float*)d_in[0];
    const float* h0     = (const float*)d_in[1];
    const float* c0     = (const float*)d_in[2];
    const float* h1     = (const float*)d_in[3];
    const float* c1     = (const float*)d_in[4];
    const float* keys   = (const float*)d_in[5];
    const float* values = (const float*)d_in[6];
    const float* qmask  = (const float*)d_in[7];
    const float* of     = (const float*)d_in[8];
    const float* W_ih0  = (const float*)d_in[9];
    const float* W_hh0  = (const float*)d_in[10];
    const float* b_ih0  = (const float*)d_in[11];
    const float* b_hh0  = (const float*)d_in[12];
    const float* W_ih1  = (const float*)d_in[13];
    const float* W_hh1  = (const float*)d_in[14];
    const float* b_ih1  = (const float*)d_in[15];
    const float* b_hh1  = (const float*)d_in[16];
    const float* W_att  = (const float*)d_in[17];
    const float* W_of   = (const float*)d_in[18];
    const int* read_ind  = (const int*)d_in[19];
    const int* write_ind = (const int*)d_in[20];
    (void)in_sizes; (void)n_in; (void)out_size;

    float* out = (float*)d_out;
    float* logits   = out;
    float* memory_t = out + (long)B_ * M_;
    float* h0n = memory_t + (long)B_ * M_ * E_;
    float* c0n = h0n + B_ * H_;
    float* h1n = c0n + B_ * H_;
    float* c1n = h1n + B_ * H_;

    static float *pX0f = nullptr, *pX1f, *pXAf, *pW0f, *pW1f, *pATT, *pBS0, *pBS1;
    static __nv_bfloat16 *pX0hi, *pX0lo, *pX1hi, *pX1lo, *pXAhi, *pXAlo,
                         *pW0hi, *pW0lo, *pW1hi, *pW1lo, *pWAhi, *pWAlo;
    if (!pX0f) {
        cudaGetSymbolAddress((void**)&pX0f, g_X0f);
        cudaGetSymbolAddress((void**)&pX1f, g_X1f);
        cudaGetSymbolAddress((void**)&pXAf, g_XAf);
        cudaGetSymbolAddress((void**)&pW0f, g_W0f);
        cudaGetSymbolAddress((void**)&pW1f, g_W1f);
        cudaGetSymbolAddress((void**)&pATT, g_ATT);
        cudaGetSymbolAddress((void**)&pBS0, g_bsum0);
        cudaGetSymbolAddress((void**)&pBS1, g_bsum1);
        cudaGetSymbolAddress((void**)&pX0hi, g_X0hi);
        cudaGetSymbolAddress((void**)&pX0lo, g_X0lo);
        cudaGetSymbolAddress((void**)&pX1hi, g_X1hi);
        cudaGetSymbolAddress((void**)&pX1lo, g_X1lo);
        cudaGetSymbolAddress((void**)&pXAhi, g_XAhi);
        cudaGetSymbolAddress((void**)&pXAlo, g_XAlo);
        cudaGetSymbolAddress((void**)&pW0hi, g_W0hi);
        cudaGetSymbolAddress((void**)&pW0lo, g_W0lo);
        cudaGetSymbolAddress((void**)&pW1hi, g_W1hi);
        cudaGetSymbolAddress((void**)&pW1lo, g_W1lo);
        cudaGetSymbolAddress((void**)&pWAhi, g_WAhi);
        cudaGetSymbolAddress((void**)&pWAlo, g_WAlo);
        cudaFuncSetAttribute(gemm_uni, cudaFuncAttributeMaxDynamicSharedMemorySize, GEMM_DYN);
    }

    convw_kernel<<<2304, 256>>>(W_ih0, W_hh0, b_ih0, b_hh0,
                                W_ih1, W_hh1, b_ih1, b_hh1, W_att);
    gather0_kernel<<<B_, 256>>>(memory, h0, h1, read_ind);

    // layer-0 GEMM + fused cell
    gemm_uni<<<dim3(16, 8), 256, GEMM_DYN>>>(pX0f, pX0hi, pX0lo, pW0f, pW0hi, pW0lo,
                                             nullptr, 0, 1, pBS0, c0, nullptr, h0n, c0n);
    // layer-1 GEMM + fused cell (+skip into O1/XA)
    gemm_uni<<<dim3(16, 8), 256, GEMM_DYN>>>(pX1f, pX1hi, pX1lo, pW1f, pW1hi, pW1lo,
                                             nullptr, 0, 2, pBS1, c1, h0n, h1n, c1n);

    attn_kernel<<<B_, 256>>>(keys, values, qmask);

    // attention-vector GEMM (tanh epilogue)
    gemm_uni<<<dim3(16, 2), 256, GEMM_DYN>>>(pXAf, pXAhi, pXAlo, W_att, pWAhi, pWAlo,
                                             pATT, 256, 0, nullptr, nullptr, nullptr,
                                             nullptr, nullptr);

    final_kernel<<<B_, 256>>>(memory, of, W_of, write_ind, logits, memory_t);
}

// round 16
// speedup vs baseline: 1.0735x; 1.0735x over previous
#include <cuda_runtime.h>
#include <cuda_bf16.h>
#include <math.h>
#include <stdint.h>

#define B_ 2048
#define M_ 128
#define E_ 256
#define H_ 256
#define S_ 64
#define F_ 4

#if defined(__CUDA_ARCH__) && (defined(__CUDA_ARCH_FEAT_SM103_ALL) || defined(__CUDA_ARCH_FEAT_SM103A_ALL))
#define TC_PATH 1
#else
#define TC_PATH 0
#endif

// ---------------- device scratch ----------------
__device__ float g_X0f[B_ * 512], g_X1f[B_ * 512], g_XAf[B_ * 512];
__device__ float g_W0f[1024 * 512], g_W1f[1024 * 512];
__device__ __nv_bfloat16 g_X0hi[B_ * 512], g_X0lo[B_ * 512];
__device__ __nv_bfloat16 g_X1hi[B_ * 512], g_X1lo[B_ * 512];
__device__ __nv_bfloat16 g_XAhi[B_ * 512], g_XAlo[B_ * 512];
__device__ __nv_bfloat16 g_W0hi[1024 * 512], g_W0lo[1024 * 512];
__device__ __nv_bfloat16 g_W1hi[1024 * 512], g_W1lo[1024 * 512];
__device__ __nv_bfloat16 g_WAhi[256 * 512], g_WAlo[256 * 512];
__device__ float g_G0[B_ * 1024], g_G1[B_ * 1024];
__device__ float g_ATT[B_ * 256];

// ---------------- helpers ----------------
__device__ __forceinline__ uint32_t smem_u32(const void* p) {
    uint32_t a;
    asm("{ .reg .u64 t; cvta.to.shared.u64 t, %1; cvt.u32.u64 %0, t; }" : "=r"(a) : "l"(p));
    return a;
}
__device__ __forceinline__ void bsplit(float x, __nv_bfloat16* hi, __nv_bfloat16* lo) {
    __nv_bfloat16 h = __float2bfloat16(x);
    *hi = h;
    *lo = __float2bfloat16(x - __bfloat162float(h));
}
__device__ __forceinline__ unsigned long long dupf(float x) {
    unsigned long long r;
    asm("mov.b64 %0, {%1, %1};" : "=l"(r) : "f"(x));
    return r;
}
__device__ __forceinline__ unsigned long long ffma2(unsigned long long a,
                                                    unsigned long long b,
                                                    unsigned long long c) {
    unsigned long long d;
    asm("fma.rn.f32x2 %0, %1, %2, %3;" : "=l"(d) : "l"(a), "l"(b), "l"(c));
    return d;
}
__device__ __forceinline__ void unpk(unsigned long long v, float& lo, float& hi) {
    asm("mov.b64 {%0, %1}, %2;" : "=f"(lo), "=f"(hi) : "l"(v));
}

#if TC_PATH
__device__ __forceinline__ uint32_t elect1() {
    uint32_t p;
    asm volatile("{\n\t.reg .pred p;\n\telect.sync _|p, 0xFFFFFFFF;\n\tselp.b32 %0,1,0,p;\n\t}" : "=r"(p));
    return p;
}
__device__ __forceinline__ void mbar_wait(uint32_t addr, uint32_t parity) {
    asm volatile(
        "{\n\t.reg .pred P;\n\t"
        "WL_%=:\n\t"
        "mbarrier.try_wait.parity.acquire.cta.shared::cta.b64 P, [%0], %1, 0x989680;\n\t"
        "@P bra.uni WD_%=;\n\t"
        "bra.uni WL_%=;\n\t"
        "WD_%=:\n\t}"
        :: "r"(addr), "r"(parity) : "memory");
}
__device__ __forceinline__ void mma_bf16_ss(uint32_t d, uint64_t da, uint64_t db,
                                            uint32_t idesc, uint32_t en) {
    asm volatile(
        "{\n\t.reg .pred p;\n\tsetp.ne.u32 p, %4, 0;\n\t"
        "tcgen05.mma.cta_group::1.kind::f16 [%0], %1, %2, %3, {%5,%5,%5,%5}, p;\n\t}"
        :: "r"(d), "l"(da), "l"(db), "r"(idesc), "r"(en), "r"(0u) : "memory");
}
__device__ __forceinline__ uint64_t mk_desc(uint32_t addr) {
    const uint64_t base = (uint64_t(2) << 61) | (uint64_t(1) << 46) |
                          (uint64_t(64) << 32) | (uint64_t(1) << 16);
    return base | ((uint64_t)(addr >> 4) & 0x3FFF);
}
#define TCLD32(r, a)                                                        \
    asm volatile(                                                           \
        "tcgen05.ld.sync.aligned.32x32b.x32.b32 "                           \
        "{%0, %1, %2, %3, %4, %5, %6, %7, "                                 \
        " %8, %9, %10, %11, %12, %13, %14, %15, "                           \
        " %16, %17, %18, %19, %20, %21, %22, %23, "                         \
        " %24, %25, %26, %27, %28, %29, %30, %31}, [%32];"                  \
        : "=r"((r)[0]), "=r"((r)[1]), "=r"((r)[2]), "=r"((r)[3]),           \
          "=r"((r)[4]), "=r"((r)[5]), "=r"((r)[6]), "=r"((r)[7]),           \
          "=r"((r)[8]), "=r"((r)[9]), "=r"((r)[10]), "=r"((r)[11]),         \
          "=r"((r)[12]), "=r"((r)[13]), "=r"((r)[14]), "=r"((r)[15]),       \
          "=r"((r)[16]), "=r"((r)[17]), "=r"((r)[18]), "=r"((r)[19]),       \
          "=r"((r)[20]), "=r"((r)[21]), "=r"((r)[22]), "=r"((r)[23]),       \
          "=r"((r)[24]), "=r"((r)[25]), "=r"((r)[26]), "=r"((r)[27]),       \
          "=r"((r)[28]), "=r"((r)[29]), "=r"((r)[30]), "=r"((r)[31])        \
        : "r"(a))
#endif  // TC_PATH

// ---------------- weight conversion ----------------
__global__ __launch_bounds__(256)
void convw_kernel(const float* __restrict__ Wih0, const float* __restrict__ Whh0,
                  const float* __restrict__ Wih1, const float* __restrict__ Whh1,
                  const float* __restrict__ Watt) {
    int n = blockIdx.x, t = threadIdx.x;
#pragma unroll
    for (int kk = 0; kk < 2; kk++) {
        int k = t + kk * 256;
        if (n < 1024) {
            float v = (k < 256) ? Wih0[n * 256 + k] : Whh0[n * 256 + k - 256];
#if !TC_PATH
            g_W0f[n * 512 + k] = v;
#endif
            bsplit(v, &g_W0hi[n * 512 + k], &g_W0lo[n * 512 + k]);
        } else if (n < 2048) {
            int m = n - 1024;
            float v = (k < 256) ? Wih1[m * 256 + k] : Whh1[m * 256 + k - 256];
#if !TC_PATH
            g_W1f[m * 512 + k] = v;
#endif
            bsplit(v, &g_W1hi[m * 512 + k], &g_W1lo[m * 512 + k]);
        } else {
            int m = n - 2048;
            float v = Watt[m * 512 + k];
            bsplit(v, &g_WAhi[m * 512 + k], &g_WAlo[m * 512 + k]);
        }
    }
}

// ---------------- gather ----------------
__global__ void gather0_kernel(const float* __restrict__ memory,
                               const float* __restrict__ h0,
                               const int* __restrict__ read_ind) {
    int b = blockIdx.x, t = threadIdx.x;
    int ri = read_ind[b];
    float x = memory[((long)b * M_ + ri) * E_ + t];
    float h = h0[b * H_ + t];
#if !TC_PATH
    g_X0f[b * 512 + t] = x;
    g_X0f[b * 512 + 256 + t] = h;
#endif
    bsplit(x, &g_X0hi[b * 512 + t], &g_X0lo[b * 512 + t]);
    bsplit(h, &g_X0hi[b * 512 + 256 + t], &g_X0lo[b * 512 + 256 + t]);
}

// ---------------- unified GEMM: C[2048,N] = A[2048,512] @ W[N,512]^T ----------------
// TC path: 128x128 tile, K chunks of 64, THREE-deep smem ring, register prefetch.
#define TSZ 16384
#define NBUF 3
#define GEMM_DYN (1024 + NBUF * 4 * TSZ)

__global__ __launch_bounds__(256)
void gemm_uni(const float* __restrict__ Af,
              const __nv_bfloat16* __restrict__ Ahi, const __nv_bfloat16* __restrict__ Alo,
              const float* __restrict__ Bf,
              const __nv_bfloat16* __restrict__ Bhi, const __nv_bfloat16* __restrict__ Blo,
              float* __restrict__ C, int ldc, int dotanh) {
    extern __shared__ char dynraw[];
#if TC_PATH
    __shared__ uint32_t s_tmem[1];
    __shared__ __align__(8) unsigned long long s_mbar[NBUF];

    int tid = threadIdx.x, wid = tid >> 5, lane = tid & 31;
    uint32_t dynb = smem_u32(dynraw);
    uint32_t tiles_a = (dynb + 1023u) & ~1023u;
    char* tiles = dynraw + (tiles_a - dynb);
    int br = blockIdx.x * 128, bc = blockIdx.y * 128;
    uint32_t mbar0 = smem_u32(&s_mbar[0]);
    const uint32_t IDESC = (1u << 4) | (1u << 7) | (1u << 10) | (16u << 17) | (8u << 24);

    if (wid == 0) {
        asm volatile("tcgen05.alloc.cta_group::1.sync.aligned.shared::cta.b32 [%0], %1;"
                     :: "r"(smem_u32(s_tmem)), "r"(128u) : "memory");
    }
    if (tid == 0) {
#pragma unroll
        for (int m = 0; m < NBUF; m++)
            asm volatile("mbarrier.init.shared.b64 [%0], 1;" :: "r"(mbar0 + m * 8) : "memory");
    }
    __syncthreads();
    uint32_t tmem;
    asm volatile("ld.shared.b32 %0, [%1];" : "=r"(tmem) : "r"(smem_u32(s_tmem)));

    const __nv_bfloat16* srcs[4] = {Ahi, Alo, Bhi, Blo};
    int rowbases[4] = {br, br, bc, bc};

    uint4 rg[4][4];
#define LOADC(kc)                                                                    \
    do {                                                                             \
        _Pragma("unroll") for (int t = 0; t < 4; t++) {                              \
            _Pragma("unroll") for (int i = 0; i < 4; i++) {                          \
                int id = tid + i * 256;                                              \
                int r = id >> 3, c8 = id & 7;                                        \
                rg[t][i] = *reinterpret_cast<const uint4*>(                          \
                    srcs[t] + (size_t)(rowbases[t] + r) * 512 + (size_t)(kc)*64 +    \
                    c8 * 8);                                                         \
            }                                                                        \
        }                                                                            \
    } while (0)

    LOADC(0);
    for (int kc = 0; kc < 8; kc++) {
        int buf = kc % NBUF;
        if (kc >= NBUF) mbar_wait(mbar0 + buf * 8, ((kc - NBUF) / NBUF) & 1);
        char* tb = tiles + buf * (4 * TSZ);
#pragma unroll
        for (int t = 0; t < 4; t++) {
            char* dst = tb + t * TSZ;
#pragma unroll
            for (int i = 0; i < 4; i++) {
                int id = tid + i * 256;
                int r = id >> 3, c8 = id & 7;
                uint32_t off = (uint32_t)(r * 128 + c8 * 16);
                off ^= (off >> 3) & 0x70;
                *reinterpret_cast<uint4*>(dst + off) = rg[t][i];
            }
        }
        asm volatile("fence.proxy.async.shared::cta;" ::: "memory");
        __syncthreads();
        if (wid == 0 && elect1()) {
            uint64_t dA0 = mk_desc(smem_u32(tb));
            uint64_t dA1 = mk_desc(smem_u32(tb + TSZ));
            uint64_t dB0 = mk_desc(smem_u32(tb + 2 * TSZ));
            uint64_t dB1 = mk_desc(smem_u32(tb + 3 * TSZ));
            uint64_t pa[3] = {dA0, dA0, dA1};
            uint64_t pb[3] = {dB0, dB1, dB0};
#pragma unroll
            for (int p = 0; p < 3; p++) {
#pragma unroll
                for (int s = 0; s < 4; s++) {
                    uint32_t en = (kc == 0 && p == 0 && s == 0) ? 0u : 1u;
                    mma_bf16_ss(tmem, pa[p] + s * 2, pb[p] + s * 2, IDESC, en);
                }
            }
            asm volatile(
                "tcgen05.commit.cta_group::1.mbarrier::arrive::one.shared::cluster.b64 [%0];"
                :: "r"(mbar0 + buf * 8) : "memory");
        }
        if (kc < 7) LOADC(kc + 1);
    }
#undef LOADC
    // drain: mbar0 committed at kc=0,3,6 (3 commits -> last wait parity 0)
    //        mbar1 committed at kc=1,4,7 (3 commits -> parity 0)
    //        mbar2 committed at kc=2,5   (2 commits -> parity 1)
    mbar_wait(mbar0, 0);
    mbar_wait(mbar0 + 8, 0);
    mbar_wait(mbar0 + 16, 1);
    asm volatile("tcgen05.fence::after_thread_sync;" ::: "memory");

    float* Ce = reinterpret_cast<float*>(tiles);
    int wsub = wid & 3, grp = wid >> 2;
    int r = wsub * 32 + lane;
#pragma unroll
    for (int j = 0; j < 2; j++) {
        int c0 = grp * 64 + j * 32;
        uint32_t dr[32];
        TCLD32(dr, tmem + c0);
        asm volatile("tcgen05.wait::ld.sync.aligned;" ::: "memory");
#pragma unroll
        for (int i = 0; i < 32; i++) {
            float v = __uint_as_float(dr[i]);
            if (dotanh) v = tanhf(v);
            Ce[r * 129 + c0 + i] = v;
        }
    }
    __syncthreads();
#pragma unroll
    for (int i = 0; i < 16; i++) {
        int id = i * 256 + tid;
        int rr = id >> 5, q = id & 31;
        float4 v;
        v.x = Ce[rr * 129 + q * 4 + 0];
        v.y = Ce[rr * 129 + q * 4 + 1];
        v.z = Ce[rr * 129 + q * 4 + 2];
        v.w = Ce[rr * 129 + q * 4 + 3];
        *reinterpret_cast<float4*>(C + (size_t)(br + rr) * ldc + bc + q * 4) = v;
    }
    __syncthreads();
    if (wid == 0) {
        asm volatile("tcgen05.relinquish_alloc_permit.cta_group::1.sync.aligned;");
        asm volatile("tcgen05.dealloc.cta_group::1.sync.aligned.b32 %0, %1;"
                     :: "r"(tmem), "r"(128u));
    }
    (void)Af; (void)Bf;
#else
    float* As = reinterpret_cast<float*>(dynraw);
    float* Bs = As + 32 * 128;
    int tid = threadIdx.x;
    int tr = tid >> 4, tc = tid & 15;
    int br = blockIdx.x * 128, bc = blockIdx.y * 128;

    unsigned long long acc[4][8];
#pragma unroll
    for (int i = 0; i < 4; i++)
#pragma unroll
        for (int j = 0; j < 8; j++) acc[i][j] = 0ull;

    float4 ra[4], rb[4];
#pragma unroll
    for (int i = 0; i < 4; i++) {
        int id = tid + i * 256;
        int r = id >> 3, c = id & 7;
        ra[i] = *reinterpret_cast<const float4*>(Af + (size_t)(br + r) * 512 + c * 4);
        rb[i] = *reinterpret_cast<const float4*>(Bf + (size_t)(bc + r) * 512 + c * 4);
    }
    for (int kc = 0; kc < 16; kc++) {
        __syncthreads();
#pragma unroll
        for (int i = 0; i < 4; i++) {
            int id = tid + i * 256;
            int r = id >> 3, c = id & 7;
            As[(c * 4 + 0) * 128 + r] = ra[i].x;
            As[(c * 4 + 1) * 128 + r] = ra[i].y;
            As[(c * 4 + 2) * 128 + r] = ra[i].z;
            As[(c * 4 + 3) * 128 + r] = ra[i].w;
            Bs[(c * 4 + 0) * 128 + r] = rb[i].x;
            Bs[(c * 4 + 1) * 128 + r] = rb[i].y;
            Bs[(c * 4 + 2) * 128 + r] = rb[i].z;
            Bs[(c * 4 + 3) * 128 + r] = rb[i].w;
        }
        if (kc < 15) {
#pragma unroll
            for (int i = 0; i < 4; i++) {
                int id = tid + i * 256;
                int r = id >> 3, c = id & 7;
                ra[i] = *reinterpret_cast<const float4*>(
                    Af + (size_t)(br + r) * 512 + (kc + 1) * 32 + c * 4);
                rb[i] = *reinterpret_cast<const float4*>(
                    Bf + (size_t)(bc + r) * 512 + (kc + 1) * 32 + c * 4);
            }
        }
        __syncthreads();
#pragma unroll
        for (int k = 0; k < 32; k++) {
            double2 a01 = *reinterpret_cast<const double2*>(As + k * 128 + tr * 8);
            double2 a23 = *reinterpret_cast<const double2*>(As + k * 128 + tr * 8 + 4);
            unsigned long long a2[4];
            a2[0] = __double_as_longlong(a01.x);
            a2[1] = __double_as_longlong(a01.y);
            a2[2] = __double_as_longlong(a23.x);
            a2[3] = __double_as_longlong(a23.y);
            float4 b0 = *reinterpret_cast<const float4*>(Bs + k * 128 + tc * 8);
            float4 b1 = *reinterpret_cast<const float4*>(Bs + k * 128 + tc * 8 + 4);
            float bv[8] = {b0.x, b0.y, b0.z, b0.w, b1.x, b1.y, b1.z, b1.w};
#pragma unroll
            for (int j = 0; j < 8; j++) {
                unsigned long long bd = dupf(bv[j]);
#pragma unroll
                for (int mp = 0; mp < 4; mp++) acc[mp][j] = ffma2(a2[mp], bd, acc[mp][j]);
            }
        }
    }
#pragma unroll
    for (int mp = 0; mp < 4; mp++) {
        float lo[8], hi[8];
#pragma unroll
        for (int j = 0; j < 8; j++) {
            unpk(acc[mp][j], lo[j], hi[j]);
            if (dotanh) { lo[j] = tanhf(lo[j]); hi[j] = tanhf(hi[j]); }
        }
        int r0 = br + tr * 8 + mp * 2;
        float4* p0 = reinterpret_cast<float4*>(C + (size_t)r0 * ldc + bc + tc * 8);
        float4* p1 = reinterpret_cast<float4*>(C + (size_t)(r0 + 1) * ldc + bc + tc * 8);
        p0[0] = make_float4(lo[0], lo[1], lo[2], lo[3]);
        p0[1] = make_float4(lo[4], lo[5], lo[6], lo[7]);
        p1[0] = make_float4(hi[0], hi[1], hi[2], hi[3]);
        p1[1] = make_float4(hi[4], hi[5], hi[6], hi[7]);
    }
    (void)Ahi; (void)Alo; (void)Bhi; (void)Blo;
#endif
}

// ---------------- LSTM cell math ----------------
__device__ __forceinline__ float sigf(float x) { return 1.f / (1.f + __expf(-x)); }

__global__ void cell0_kernel(const float* __restrict__ b_ih, const float* __restrict__ b_hh,
                             const float* __restrict__ c_prev,
                             const float* __restrict__ h1_in,
                             float* __restrict__ h_out, float* __restrict__ c_out) {
    int b = blockIdx.x, j = threadIdx.x;
    const float* g = g_G0 + (size_t)b * 1024;
    float gi = g[j]       + b_ih[j]       + b_hh[j];
    float gf = g[256 + j] + b_ih[256 + j] + b_hh[256 + j];
    float gg = g[512 + j] + b_ih[512 + j] + b_hh[512 + j];
    float go = g[768 + j] + b_ih[768 + j] + b_hh[768 + j];
    float i_ = sigf(gi), f_ = sigf(gf), o_ = sigf(go), gv = tanhf(gg);
    float c = f_ * c_prev[b * 256 + j] + i_ * gv;
    float h = o_ * tanhf(c);
    h_out[b * 256 + j] = h;
    c_out[b * 256 + j] = c;
    float h1v = h1_in[b * 256 + j];
#if !TC_PATH
    g_X1f[b * 512 + j] = h;
    g_X1f[b * 512 + 256 + j] = h1v;
#endif
    bsplit(h, &g_X1hi[b * 512 + j], &g_X1lo[b * 512 + j]);
    bsplit(h1v, &g_X1hi[b * 512 + 256 + j], &g_X1lo[b * 512 + 256 + j]);
}

// ---------------- fused cell1 + attention ----------------
__global__ __launch_bounds__(256)
void cellattn_kernel(const float* __restrict__ b_ih, const float* __restrict__ b_hh,
                     const float* __restrict__ c_prev,
                     const float* __restrict__ h0n,
                     const float* __restrict__ keys,
                     const float* __restrict__ values,
                     const float* __restrict__ qmask,
                     float* __restrict__ h_out, float* __restrict__ c_out) {
    int b = blockIdx.x;
    int tid = threadIdx.x, warp = tid >> 5, lane = tid & 31;
    __shared__ float so1[256];
    __shared__ float sw[64];

    {
        int j = tid;
        const float* g = g_G1 + (size_t)b * 1024;
        float gi = g[j]       + b_ih[j]       + b_hh[j];
        float gf = g[256 + j] + b_ih[256 + j] + b_hh[256 + j];
        float gg = g[512 + j] + b_ih[512 + j] + b_hh[512 + j];
        float go = g[768 + j] + b_ih[768 + j] + b_hh[768 + j];
        float i_ = sigf(gi), f_ = sigf(gf), o_ = sigf(go), gv = tanhf(gg);
        float c = f_ * c_prev[b * 256 + j] + i_ * gv;
        float h = o_ * tanhf(c);
        h_out[b * 256 + j] = h;
        c_out[b * 256 + j] = c;
        float o1 = h + h0n[b * 256 + j];
        so1[j] = o1;
#if !TC_PATH
        g_XAf[b * 512 + j] = o1;
#endif
        bsplit(o1, &g_XAhi[b * 512 + j], &g_XAlo[b * 512 + j]);
    }
    __syncthreads();

#pragma unroll
    for (int i = 0; i < 8; i++) {
        int s = warp * 8 + i;
        const float* kp = keys + ((long)b * S_ + s) * H_;
        float acc = 0.f;
#pragma unroll
        for (int j = 0; j < 8; j++) acc += kp[lane + 32 * j] * so1[lane + 32 * j];
#pragma unroll
        for (int o = 16; o > 0; o >>= 1) acc += __shfl_xor_sync(0xFFFFFFFFu, acc, o);
        if (lane == 0)
            sw[s] = (qmask[b * S_ + s] > 0.f) ? acc : -INFINITY;
    }
    __syncthreads();
    if (warp == 0) {
        float v0 = sw[lane], v1 = sw[lane + 32];
        float mx = fmaxf(v0, v1);
#pragma unroll
        for (int o = 16; o > 0; o >>= 1) mx = fmaxf(mx, __shfl_xor_sync(0xFFFFFFFFu, mx, o));
        float e0 = __expf(v0 - mx), e1 = __expf(v1 - mx);
        float s = e0 + e1;
#pragma unroll
        for (int o = 16; o > 0; o >>= 1) s += __shfl_xor_sync(0xFFFFFFFFu, s, o);
        float inv = 1.f / s;
        sw[lane] = e0 * inv;
        sw[lane + 32] = e1 * inv;
    }
    __syncthreads();
    float acc = 0.f;
    const float* vp = values + (long)b * S_ * E_ + tid;
#pragma unroll 8
    for (int s2 = 0; s2 < S_; s2++) acc += sw[s2] * vp[s2 * E_];
#if !TC_PATH
    g_XAf[b * 512 + 256 + tid] = acc;
#endif
    bsplit(acc, &g_XAhi[b * 512 + 256 + tid], &g_XAlo[b * 512 + 256 + tid]);
}

// ---------------- fused final pass (single read of memory) ----------------
__global__ __launch_bounds__(256)
void final_kernel(const float* __restrict__ memory,
                  const float* __restrict__ of,
                  const float* __restrict__ W_of,
                  const int* __restrict__ write_ind,
                  float* __restrict__ logits,
                  float* __restrict__ memory_t) {
    int b = blockIdx.x;
    int tid = threadIdx.x, warp = tid >> 5, lane = tid & 31;
    __shared__ float sa[256];
    __shared__ float swof[4];
    sa[tid] = g_ATT[b * 256 + tid];
    if (tid < 4) swof[tid] = W_of[tid];
    __syncthreads();

    int wi_raw = write_ind[b];
    float wmask = (wi_raw >= 0) ? 1.f : 0.f;
    int wi = (wi_raw >= 0) ? wi_raw : 0;

    for (int m = warp; m < M_; m += 8) {
        const float* mp = memory + ((long)b * M_ + m) * E_;
        float* mo = memory_t + ((long)b * M_ + m) * E_;
        float addf = (m == wi) ? wmask : 0.f;
        float acc = 0.f;
#pragma unroll
        for (int h = 0; h < 2; h++) {
            int e = lane * 4 + h * 128;
            float4 mv = *reinterpret_cast<const float4*>(mp + e);
            float4 av = *reinterpret_cast<const float4*>(sa + e);
            acc += mv.x * av.x + mv.y * av.y + mv.z * av.z + mv.w * av.w;
            float4 ov;
            ov.x = mv.x + addf * av.x; ov.y = mv.y + addf * av.y;
            ov.z = mv.z + addf * av.z; ov.w = mv.w + addf * av.w;
            *reinterpret_cast<float4*>(mo + e) = ov;
        }
#pragma unroll
        for (int o = 16; o > 0; o >>= 1) acc += __shfl_xor_sync(0xFFFFFFFFu, acc, o);
        if (lane == 0) {
            const float* ofp = of + ((long)b * M_ + m) * F_;
            acc += ofp[0] * swof[0] + ofp[1] * swof[1] + ofp[2] * swof[2] + ofp[3] * swof[3];
            logits[b * M_ + m] = acc;
        }
    }
}

// ---------------- launch ----------------
extern "C" void kernel_launch(void* const* d_in, const int* in_sizes, int n_in,
                              void* d_out, int out_size) {
    const float* memory = (const float*)d_in[0];
    const float* h0     = (const float*)d_in[1];
    const float* c0     = (const float*)d_in[2];
    const float* h1     = (const float*)d_in[3];
    const float* c1     = (const float*)d_in[4];
    const float* keys   = (const float*)d_in[5];
    const float* values = (const float*)d_in[6];
    const float* qmask  = (const float*)d_in[7];
    const float* of     = (const float*)d_in[8];
    const float* W_ih0  = (const float*)d_in[9];
    const float* W_hh0  = (const float*)d_in[10];
    const float* b_ih0  = (const float*)d_in[11];
    const float* b_hh0  = (const float*)d_in[12];
    const float* W_ih1  = (const float*)d_in[13];
    const float* W_hh1  = (const float*)d_in[14];
    const float* b_ih1  = (const float*)d_in[15];
    const float* b_hh1  = (const float*)d_in[16];
    const float* W_att  = (const float*)d_in[17];
    const float* W_of   = (const float*)d_in[18];
    const int* read_ind  = (const int*)d_in[19];
    const int* write_ind = (const int*)d_in[20];
    (void)in_sizes; (void)n_in; (void)out_size;

    float* out = (float*)d_out;
    float* logits   = out;
    float* memory_t = out + (long)B_ * M_;
    float* h0n = memory_t + (long)B_ * M_ * E_;
    float* c0n = h0n + B_ * H_;
    float* h1n = c0n + B_ * H_;
    float* c1n = h1n + B_ * H_;

    static float *pX0f = nullptr, *pX1f, *pXAf, *pW0f, *pW1f, *pG0, *pG1, *pATT;
    static __nv_bfloat16 *pX0hi, *pX0lo, *pX1hi, *pX1lo, *pXAhi, *pXAlo,
                         *pW0hi, *pW0lo, *pW1hi, *pW1lo, *pWAhi, *pWAlo;
    if (!pX0f) {
        cudaGetSymbolAddress((void**)&pX0f, g_X0f);
        cudaGetSymbolAddress((void**)&pX1f, g_X1f);
        cudaGetSymbolAddress((void**)&pXAf, g_XAf);
        cudaGetSymbolAddress((void**)&pW0f, g_W0f);
        cudaGetSymbolAddress((void**)&pW1f, g_W1f);
        cudaGetSymbolAddress((void**)&pG0, g_G0);
        cudaGetSymbolAddress((void**)&pG1, g_G1);
        cudaGetSymbolAddress((void**)&pATT, g_ATT);
        cudaGetSymbolAddress((void**)&pX0hi, g_X0hi);
        cudaGetSymbolAddress((void**)&pX0lo, g_X0lo);
        cudaGetSymbolAddress((void**)&pX1hi, g_X1hi);
        cudaGetSymbolAddress((void**)&pX1lo, g_X1lo);
        cudaGetSymbolAddress((void**)&pXAhi, g_XAhi);
        cudaGetSymbolAddress((void**)&pXAlo, g_XAlo);
        cudaGetSymbolAddress((void**)&pW0hi, g_W0hi);
        cudaGetSymbolAddress((void**)&pW0lo, g_W0lo);
        cudaGetSymbolAddress((void**)&pW1hi, g_W1hi);
        cudaGetSymbolAddress((void**)&pW1lo, g_W1lo);
        cudaGetSymbolAddress((void**)&pWAhi, g_WAhi);
        cudaGetSymbolAddress((void**)&pWAlo, g_WAlo);
        cudaFuncSetAttribute(gemm_uni, cudaFuncAttributeMaxDynamicSharedMemorySize, GEMM_DYN);
    }

    convw_kernel<<<2304, 256>>>(W_ih0, W_hh0, W_ih1, W_hh1, W_att);
    gather0_kernel<<<B_, 256>>>(memory, h0, read_ind);

    gemm_uni<<<dim3(16, 8), 256, GEMM_DYN>>>(pX0f, pX0hi, pX0lo, pW0f, pW0hi, pW0lo,
                                             pG0, 1024, 0);
    cell0_kernel<<<B_, 256>>>(b_ih0, b_hh0, c0, h1, h0n, c0n);

    gemm_uni<<<dim3(16, 8), 256, GEMM_DYN>>>(pX1f, pX1hi, pX1lo, pW1f, pW1hi, pW1lo,
                                             pG1, 1024, 0);
    cellattn_kernel<<<B_, 256>>>(b_ih1, b_hh1, c1, h0n, keys, values, qmask, h1n, c1n);

    gemm_uni<<<dim3(16, 2), 256, GEMM_DYN>>>(pXAf, pXAhi, pXAlo, W_att, pWAhi, pWAlo,
                                             pATT, 256, 1);

    final_kernel<<<B_, 256>>>(memory, of, W_of, write_ind, logits, memory_t);
}

// round 17
// speedup vs baseline: 1.0960x; 1.0209x over previous
#include <cuda_runtime.h>
#include <cuda_bf16.h>
#include <math.h>
#include <stdint.h>

#define B_ 2048
#define M_ 128
#define E_ 256
#define H_ 256
#define S_ 64
#define F_ 4

#if defined(__CUDA_ARCH__) && (defined(__CUDA_ARCH_FEAT_SM103_ALL) || defined(__CUDA_ARCH_FEAT_SM103A_ALL))
#define TC_PATH 1
#else
#define TC_PATH 0
#endif

// ---------------- device scratch ----------------
__device__ float g_X0f[B_ * 512], g_X1f[B_ * 512], g_XAf[B_ * 512];
__device__ float g_W0f[1024 * 512], g_W1f[1024 * 512];
__device__ __nv_bfloat16 g_X0hi[B_ * 512], g_X0lo[B_ * 512];
__device__ __nv_bfloat16 g_X1hi[B_ * 512], g_X1lo[B_ * 512];
__device__ __nv_bfloat16 g_XAhi[B_ * 512], g_XAlo[B_ * 512];
__device__ __nv_bfloat16 g_W0hi[1024 * 512], g_W0lo[1024 * 512];
__device__ __nv_bfloat16 g_W1hi[1024 * 512], g_W1lo[1024 * 512];
__device__ __nv_bfloat16 g_WAhi[256 * 512], g_WAlo[256 * 512];
__device__ float g_G0[B_ * 1024], g_G1[B_ * 1024];
__device__ float g_ATT[B_ * 256];

// ---------------- helpers ----------------
__device__ __forceinline__ uint32_t smem_u32(const void* p) {
    uint32_t a;
    asm("{ .reg .u64 t; cvta.to.shared.u64 t, %1; cvt.u32.u64 %0, t; }" : "=r"(a) : "l"(p));
    return a;
}
__device__ __forceinline__ void bsplit(float x, __nv_bfloat16* hi, __nv_bfloat16* lo) {
    __nv_bfloat16 h = __float2bfloat16(x);
    *hi = h;
    *lo = __float2bfloat16(x - __bfloat162float(h));
}
__device__ __forceinline__ float tanh_fast(float x) {
    float y;
    asm("tanh.approx.f32 %0, %1;" : "=f"(y) : "f"(x));
    return y;
}
__device__ __forceinline__ float sigf(float x) {
    return 0.5f * tanh_fast(0.5f * x) + 0.5f;
}
__device__ __forceinline__ unsigned long long dupf(float x) {
    unsigned long long r;
    asm("mov.b64 %0, {%1, %1};" : "=l"(r) : "f"(x));
    return r;
}
__device__ __forceinline__ unsigned long long ffma2(unsigned long long a,
                                                    unsigned long long b,
                                                    unsigned long long c) {
    unsigned long long d;
    asm("fma.rn.f32x2 %0, %1, %2, %3;" : "=l"(d) : "l"(a), "l"(b), "l"(c));
    return d;
}
__device__ __forceinline__ void unpk(unsigned long long v, float& lo, float& hi) {
    asm("mov.b64 {%0, %1}, %2;" : "=f"(lo), "=f"(hi) : "l"(v));
}

#if TC_PATH
__device__ __forceinline__ uint32_t elect1() {
    uint32_t p;
    asm volatile("{\n\t.reg .pred p;\n\telect.sync _|p, 0xFFFFFFFF;\n\tselp.b32 %0,1,0,p;\n\t}" : "=r"(p));
    return p;
}
__device__ __forceinline__ void mbar_wait(uint32_t addr, uint32_t parity) {
    asm volatile(
        "{\n\t.reg .pred P;\n\t"
        "WL_%=:\n\t"
        "mbarrier.try_wait.parity.acquire.cta.shared::cta.b64 P, [%0], %1, 0x989680;\n\t"
        "@P bra.uni WD_%=;\n\t"
        "bra.uni WL_%=;\n\t"
        "WD_%=:\n\t}"
        :: "r"(addr), "r"(parity) : "memory");
}
__device__ __forceinline__ void mma_bf16_ss(uint32_t d, uint64_t da, uint64_t db,
                                            uint32_t idesc, uint32_t en) {
    asm volatile(
        "{\n\t.reg .pred p;\n\tsetp.ne.u32 p, %4, 0;\n\t"
        "tcgen05.mma.cta_group::1.kind::f16 [%0], %1, %2, %3, {%5,%5,%5,%5}, p;\n\t}"
        :: "r"(d), "l"(da), "l"(db), "r"(idesc), "r"(en), "r"(0u) : "memory");
}
__device__ __forceinline__ uint64_t mk_desc(uint32_t addr) {
    const uint64_t base = (uint64_t(2) << 61) | (uint64_t(1) << 46) |
                          (uint64_t(64) << 32) | (uint64_t(1) << 16);
    return base | ((uint64_t)(addr >> 4) & 0x3FFF);
}
#define TCLD32(r, a)                                                        \
    asm volatile(                                                           \
        "tcgen05.ld.sync.aligned.32x32b.x32.b32 "                           \
        "{%0, %1, %2, %3, %4, %5, %6, %7, "                                 \
        " %8, %9, %10, %11, %12, %13, %14, %15, "                           \
        " %16, %17, %18, %19, %20, %21, %22, %23, "                         \
        " %24, %25, %26, %27, %28, %29, %30, %31}, [%32];"                  \
        : "=r"((r)[0]), "=r"((r)[1]), "=r"((r)[2]), "=r"((r)[3]),           \
          "=r"((r)[4]), "=r"((r)[5]), "=r"((r)[6]), "=r"((r)[7]),           \
          "=r"((r)[8]), "=r"((r)[9]), "=r"((r)[10]), "=r"((r)[11]),         \
          "=r"((r)[12]), "=r"((r)[13]), "=r"((r)[14]), "=r"((r)[15]),       \
          "=r"((r)[16]), "=r"((r)[17]), "=r"((r)[18]), "=r"((r)[19]),       \
          "=r"((r)[20]), "=r"((r)[21]), "=r"((r)[22]), "=r"((r)[23]),       \
          "=r"((r)[24]), "=r"((r)[25]), "=r"((r)[26]), "=r"((r)[27]),       \
          "=r"((r)[28]), "=r"((r)[29]), "=r"((r)[30]), "=r"((r)[31])        \
        : "r"(a))
#endif  // TC_PATH

// ---------------- weight conversion ----------------
__global__ __launch_bounds__(256)
void convw_kernel(const float* __restrict__ Wih0, const float* __restrict__ Whh0,
                  const float* __restrict__ Wih1, const float* __restrict__ Whh1,
                  const float* __restrict__ Watt) {
    int n = blockIdx.x, t = threadIdx.x;
#pragma unroll
    for (int kk = 0; kk < 2; kk++) {
        int k = t + kk * 256;
        if (n < 1024) {
            float v = (k < 256) ? Wih0[n * 256 + k] : Whh0[n * 256 + k - 256];
#if !TC_PATH
            g_W0f[n * 512 + k] = v;
#endif
            bsplit(v, &g_W0hi[n * 512 + k], &g_W0lo[n * 512 + k]);
        } else if (n < 2048) {
            int m = n - 1024;
            float v = (k < 256) ? Wih1[m * 256 + k] : Whh1[m * 256 + k - 256];
#if !TC_PATH
            g_W1f[m * 512 + k] = v;
#endif
            bsplit(v, &g_W1hi[m * 512 + k], &g_W1lo[m * 512 + k]);
        } else {
            int m = n - 2048;
            float v = Watt[m * 512 + k];
            bsplit(v, &g_WAhi[m * 512 + k], &g_WAlo[m * 512 + k]);
        }
    }
}

// ---------------- gather ----------------
__global__ void gather0_kernel(const float* __restrict__ memory,
                               const float* __restrict__ h0,
                               const int* __restrict__ read_ind) {
    int b = blockIdx.x, t = threadIdx.x;
    int ri = read_ind[b];
    float x = memory[((long)b * M_ + ri) * E_ + t];
    float h = h0[b * H_ + t];
#if !TC_PATH
    g_X0f[b * 512 + t] = x;
    g_X0f[b * 512 + 256 + t] = h;
#endif
    bsplit(x, &g_X0hi[b * 512 + t], &g_X0lo[b * 512 + t]);
    bsplit(h, &g_X0hi[b * 512 + 256 + t], &g_X0lo[b * 512 + 256 + t]);
}

// ---------------- unified GEMM: C[2048,N] = A[2048,512] @ W[N,512]^T ----------------
#define TSZ 16384
#define GEMM_DYN (1024 + 8 * TSZ)

__global__ __launch_bounds__(256)
void gemm_uni(const float* __restrict__ Af,
              const __nv_bfloat16* __restrict__ Ahi, const __nv_bfloat16* __restrict__ Alo,
              const float* __restrict__ Bf,
              const __nv_bfloat16* __restrict__ Bhi, const __nv_bfloat16* __restrict__ Blo,
              float* __restrict__ C, int ldc, int dotanh) {
    extern __shared__ char dynraw[];
#if TC_PATH
    __shared__ uint32_t s_tmem[1];
    __shared__ __align__(8) unsigned long long s_mbar[2];

    int tid = threadIdx.x, wid = tid >> 5, lane = tid & 31;
    uint32_t dynb = smem_u32(dynraw);
    uint32_t tiles_a = (dynb + 1023u) & ~1023u;
    char* tiles = dynraw + (tiles_a - dynb);
    int br = blockIdx.x * 128, bc = blockIdx.y * 128;
    uint32_t mbar0 = smem_u32(&s_mbar[0]);
    const uint32_t IDESC = (1u << 4) | (1u << 7) | (1u << 10) | (16u << 17) | (8u << 24);

    if (wid == 0) {
        asm volatile("tcgen05.alloc.cta_group::1.sync.aligned.shared::cta.b32 [%0], %1;"
                     :: "r"(smem_u32(s_tmem)), "r"(128u) : "memory");
    }
    if (tid == 0) {
        asm volatile("mbarrier.init.shared.b64 [%0], 1;" :: "r"(mbar0) : "memory");
        asm volatile("mbarrier.init.shared.b64 [%0], 1;" :: "r"(mbar0 + 8) : "memory");
    }
    __syncthreads();
    uint32_t tmem;
    asm volatile("ld.shared.b32 %0, [%1];" : "=r"(tmem) : "r"(smem_u32(s_tmem)));

    const __nv_bfloat16* srcs[4] = {Ahi, Alo, Bhi, Blo};
    int rowbases[4] = {br, br, bc, bc};

    uint4 rg[4][4];
#define LOADC(kc)                                                                    \
    do {                                                                             \
        _Pragma("unroll") for (int t = 0; t < 4; t++) {                              \
            _Pragma("unroll") for (int i = 0; i < 4; i++) {                          \
                int id = tid + i * 256;                                              \
                int r = id >> 3, c8 = id & 7;                                        \
                rg[t][i] = *reinterpret_cast<const uint4*>(                          \
                    srcs[t] + (size_t)(rowbases[t] + r) * 512 + (size_t)(kc)*64 +    \
                    c8 * 8);                                                         \
            }                                                                        \
        }                                                                            \
    } while (0)

    LOADC(0);
    for (int kc = 0; kc < 8; kc++) {
        int buf = kc & 1;
        if (kc >= 2) mbar_wait(mbar0 + buf * 8, ((kc - 2) >> 1) & 1);
        char* tb = tiles + buf * (4 * TSZ);
#pragma unroll
        for (int t = 0; t < 4; t++) {
            char* dst = tb + t * TSZ;
#pragma unroll
            for (int i = 0; i < 4; i++) {
                int id = tid + i * 256;
                int r = id >> 3, c8 = id & 7;
                uint32_t off = (uint32_t)(r * 128 + c8 * 16);
                off ^= (off >> 3) & 0x70;
                *reinterpret_cast<uint4*>(dst + off) = rg[t][i];
            }
        }
        asm volatile("fence.proxy.async.shared::cta;" ::: "memory");
        __syncthreads();
        if (wid == 0 && elect1()) {
            uint64_t dA0 = mk_desc(smem_u32(tb));
            uint64_t dA1 = mk_desc(smem_u32(tb + TSZ));
            uint64_t dB0 = mk_desc(smem_u32(tb + 2 * TSZ));
            uint64_t dB1 = mk_desc(smem_u32(tb + 3 * TSZ));
            uint64_t pa[3] = {dA0, dA0, dA1};
            uint64_t pb[3] = {dB0, dB1, dB0};
#pragma unroll
            for (int p = 0; p < 3; p++) {
#pragma unroll
                for (int s = 0; s < 4; s++) {
                    uint32_t en = (kc == 0 && p == 0 && s == 0) ? 0u : 1u;
                    mma_bf16_ss(tmem, pa[p] + s * 2, pb[p] + s * 2, IDESC, en);
                }
            }
            asm volatile(
                "tcgen05.commit.cta_group::1.mbarrier::arrive::one.shared::cluster.b64 [%0];"
                :: "r"(mbar0 + buf * 8) : "memory");
        }
        if (kc < 7) LOADC(kc + 1);
    }
#undef LOADC
    mbar_wait(mbar0, 1);
    mbar_wait(mbar0 + 8, 1);
    asm volatile("tcgen05.fence::after_thread_sync;" ::: "memory");

    float* Ce = reinterpret_cast<float*>(tiles);
    int wsub = wid & 3, grp = wid >> 2;
    int r = wsub * 32 + lane;
#pragma unroll
    for (int j = 0; j < 2; j++) {
        int c0 = grp * 64 + j * 32;
        uint32_t dr[32];
        TCLD32(dr, tmem + c0);
        asm volatile("tcgen05.wait::ld.sync.aligned;" ::: "memory");
#pragma unroll
        for (int i = 0; i < 32; i++) {
            float v = __uint_as_float(dr[i]);
            if (dotanh) v = tanh_fast(v);
            Ce[r * 129 + c0 + i] = v;
        }
    }
    __syncthreads();
#pragma unroll
    for (int i = 0; i < 16; i++) {
        int id = i * 256 + tid;
        int rr = id >> 5, q = id & 31;
        float4 v;
        v.x = Ce[rr * 129 + q * 4 + 0];
        v.y = Ce[rr * 129 + q * 4 + 1];
        v.z = Ce[rr * 129 + q * 4 + 2];
        v.w = Ce[rr * 129 + q * 4 + 3];
        *reinterpret_cast<float4*>(C + (size_t)(br + rr) * ldc + bc + q * 4) = v;
    }
    __syncthreads();
    if (wid == 0) {
        asm volatile("tcgen05.relinquish_alloc_permit.cta_group::1.sync.aligned;");
        asm volatile("tcgen05.dealloc.cta_group::1.sync.aligned.b32 %0, %1;"
                     :: "r"(tmem), "r"(128u));
    }
    (void)Af; (void)Bf;
#else
    float* As = reinterpret_cast<float*>(dynraw);
    float* Bs = As + 32 * 128;
    int tid = threadIdx.x;
    int tr = tid >> 4, tc = tid & 15;
    int br = blockIdx.x * 128, bc = blockIdx.y * 128;

    unsigned long long acc[4][8];
#pragma unroll
    for (int i = 0; i < 4; i++)
#pragma unroll
        for (int j = 0; j < 8; j++) acc[i][j] = 0ull;

    float4 ra[4], rb[4];
#pragma unroll
    for (int i = 0; i < 4; i++) {
        int id = tid + i * 256;
        int r = id >> 3, c = id & 7;
        ra[i] = *reinterpret_cast<const float4*>(Af + (size_t)(br + r) * 512 + c * 4);
        rb[i] = *reinterpret_cast<const float4*>(Bf + (size_t)(bc + r) * 512 + c * 4);
    }
    for (int kc = 0; kc < 16; kc++) {
        __syncthreads();
#pragma unroll
        for (int i = 0; i < 4; i++) {
            int id = tid + i * 256;
            int r = id >> 3, c = id & 7;
            As[(c * 4 + 0) * 128 + r] = ra[i].x;
            As[(c * 4 + 1) * 128 + r] = ra[i].y;
            As[(c * 4 + 2) * 128 + r] = ra[i].z;
            As[(c * 4 + 3) * 128 + r] = ra[i].w;
            Bs[(c * 4 + 0) * 128 + r] = rb[i].x;
            Bs[(c * 4 + 1) * 128 + r] = rb[i].y;
            Bs[(c * 4 + 2) * 128 + r] = rb[i].z;
            Bs[(c * 4 + 3) * 128 + r] = rb[i].w;
        }
        if (kc < 15) {
#pragma unroll
            for (int i = 0; i < 4; i++) {
                int id = tid + i * 256;
                int r = id >> 3, c = id & 7;
                ra[i] = *reinterpret_cast<const float4*>(
                    Af + (size_t)(br + r) * 512 + (kc + 1) * 32 + c * 4);
                rb[i] = *reinterpret_cast<const float4*>(
                    Bf + (size_t)(bc + r) * 512 + (kc + 1) * 32 + c * 4);
            }
        }
        __syncthreads();
#pragma unroll
        for (int k = 0; k < 32; k++) {
            double2 a01 = *reinterpret_cast<const double2*>(As + k * 128 + tr * 8);
            double2 a23 = *reinterpret_cast<const double2*>(As + k * 128 + tr * 8 + 4);
            unsigned long long a2[4];
            a2[0] = __double_as_longlong(a01.x);
            a2[1] = __double_as_longlong(a01.y);
            a2[2] = __double_as_longlong(a23.x);
            a2[3] = __double_as_longlong(a23.y);
            float4 b0 = *reinterpret_cast<const float4*>(Bs + k * 128 + tc * 8);
            float4 b1 = *reinterpret_cast<const float4*>(Bs + k * 128 + tc * 8 + 4);
            float bv[8] = {b0.x, b0.y, b0.z, b0.w, b1.x, b1.y, b1.z, b1.w};
#pragma unroll
            for (int j = 0; j < 8; j++) {
                unsigned long long bd = dupf(bv[j]);
#pragma unroll
                for (int mp = 0; mp < 4; mp++) acc[mp][j] = ffma2(a2[mp], bd, acc[mp][j]);
            }
        }
    }
#pragma unroll
    for (int mp = 0; mp < 4; mp++) {
        float lo[8], hi[8];
#pragma unroll
        for (int j = 0; j < 8; j++) {
            unpk(acc[mp][j], lo[j], hi[j]);
            if (dotanh) { lo[j] = tanh_fast(lo[j]); hi[j] = tanh_fast(hi[j]); }
        }
        int r0 = br + tr * 8 + mp * 2;
        float4* p0 = reinterpret_cast<float4*>(C + (size_t)r0 * ldc + bc + tc * 8);
        float4* p1 = reinterpret_cast<float4*>(C + (size_t)(r0 + 1) * ldc + bc + tc * 8);
        p0[0] = make_float4(lo[0], lo[1], lo[2], lo[3]);
        p0[1] = make_float4(lo[4], lo[5], lo[6], lo[7]);
        p1[0] = make_float4(hi[0], hi[1], hi[2], hi[3]);
        p1[1] = make_float4(hi[4], hi[5], hi[6], hi[7]);
    }
    (void)Ahi; (void)Alo; (void)Bhi; (void)Blo;
#endif
}

// ---------------- LSTM cell math ----------------
__global__ void cell0_kernel(const float* __restrict__ b_ih, const float* __restrict__ b_hh,
                             const float* __restrict__ c_prev,
                             const float* __restrict__ h1_in,
                             float* __restrict__ h_out, float* __restrict__ c_out) {
    int b = blockIdx.x, j = threadIdx.x;
    const float* g = g_G0 + (size_t)b * 1024;
    float gi = g[j]       + b_ih[j]       + b_hh[j];
    float gf = g[256 + j] + b_ih[256 + j] + b_hh[256 + j];
    float gg = g[512 + j] + b_ih[512 + j] + b_hh[512 + j];
    float go = g[768 + j] + b_ih[768 + j] + b_hh[768 + j];
    float i_ = sigf(gi), f_ = sigf(gf), o_ = sigf(go), gv = tanh_fast(gg);
    float c = f_ * c_prev[b * 256 + j] + i_ * gv;
    float h = o_ * tanh_fast(c);
    h_out[b * 256 + j] = h;
    c_out[b * 256 + j] = c;
    float h1v = h1_in[b * 256 + j];
#if !TC_PATH
    g_X1f[b * 512 + j] = h;
    g_X1f[b * 512 + 256 + j] = h1v;
#endif
    bsplit(h, &g_X1hi[b * 512 + j], &g_X1lo[b * 512 + j]);
    bsplit(h1v, &g_X1hi[b * 512 + 256 + j], &g_X1lo[b * 512 + 256 + j]);
}

// ---------------- fused cell1 + attention ----------------
__global__ __launch_bounds__(256)
void cellattn_kernel(const float* __restrict__ b_ih, const float* __restrict__ b_hh,
                     const float* __restrict__ c_prev,
                     const float* __restrict__ h0n,
                     const float* __restrict__ keys,
                     const float* __restrict__ values,
                     const float* __restrict__ qmask,
                     float* __restrict__ h_out, float* __restrict__ c_out) {
    int b = blockIdx.x;
    int tid = threadIdx.x, warp = tid >> 5, lane = tid & 31;
    __shared__ float so1[256];
    __shared__ float sw[64];

    {
        int j = tid;
        const float* g = g_G1 + (size_t)b * 1024;
        float gi = g[j]       + b_ih[j]       + b_hh[j];
        float gf = g[256 + j] + b_ih[256 + j] + b_hh[256 + j];
        float gg = g[512 + j] + b_ih[512 + j] + b_hh[512 + j];
        float go = g[768 + j] + b_ih[768 + j] + b_hh[768 + j];
        float i_ = sigf(gi), f_ = sigf(gf), o_ = sigf(go), gv = tanh_fast(gg);
        float c = f_ * c_prev[b * 256 + j] + i_ * gv;
        float h = o_ * tanh_fast(c);
        h_out[b * 256 + j] = h;
        c_out[b * 256 + j] = c;
        float o1 = h + h0n[b * 256 + j];
        so1[j] = o1;
#if !TC_PATH
        g_XAf[b * 512 + j] = o1;
#endif
        bsplit(o1, &g_XAhi[b * 512 + j], &g_XAlo[b * 512 + j]);
    }
    __syncthreads();

#pragma unroll
    for (int i = 0; i < 8; i++) {
        int s = warp * 8 + i;
        const float* kp = keys + ((long)b * S_ + s) * H_;
        float acc = 0.f;
#pragma unroll
        for (int j = 0; j < 8; j++) acc += kp[lane + 32 * j] * so1[lane + 32 * j];
#pragma unroll
        for (int o = 16; o > 0; o >>= 1) acc += __shfl_xor_sync(0xFFFFFFFFu, acc, o);
        if (lane == 0)
            sw[s] = (qmask[b * S_ + s] > 0.f) ? acc : -INFINITY;
    }
    __syncthreads();
    if (warp == 0) {
        float v0 = sw[lane], v1 = sw[lane + 32];
        float mx = fmaxf(v0, v1);
#pragma unroll
        for (int o = 16; o > 0; o >>= 1) mx = fmaxf(mx, __shfl_xor_sync(0xFFFFFFFFu, mx, o));
        float e0 = __expf(v0 - mx), e1 = __expf(v1 - mx);
        float s = e0 + e1;
#pragma unroll
        for (int o = 16; o > 0; o >>= 1) s += __shfl_xor_sync(0xFFFFFFFFu, s, o);
        float inv = 1.f / s;
        sw[lane] = e0 * inv;
        sw[lane + 32] = e1 * inv;
    }
    __syncthreads();
    float acc = 0.f;
    const float* vp = values + (long)b * S_ * E_ + tid;
#pragma unroll 8
    for (int s2 = 0; s2 < S_; s2++) acc += sw[s2] * vp[s2 * E_];
#if !TC_PATH
    g_XAf[b * 512 + 256 + tid] = acc;
#endif
    bsplit(acc, &g_XAhi[b * 512 + 256 + tid], &g_XAlo[b * 512 + 256 + tid]);
}

// ---------------- fused final pass (single read of memory) ----------------
__global__ __launch_bounds__(256)
void final_kernel(const float* __restrict__ memory,
                  const float* __restrict__ of,
                  const float* __restrict__ W_of,
                  const int* __restrict__ write_ind,
                  float* __restrict__ logits,
                  float* __restrict__ memory_t) {
    int b = blockIdx.x;
    int tid = threadIdx.x, warp = tid >> 5, lane = tid & 31;
    __shared__ float sa[256];
    __shared__ float swof[4];
    sa[tid] = g_ATT[b * 256 + tid];
    if (tid < 4) swof[tid] = W_of[tid];
    __syncthreads();

    int wi_raw = write_ind[b];
    float wmask = (wi_raw >= 0) ? 1.f : 0.f;
    int wi = (wi_raw >= 0) ? wi_raw : 0;

    for (int m = warp; m < M_; m += 8) {
        const float* mp = memory + ((long)b * M_ + m) * E_;
        float* mo = memory_t + ((long)b * M_ + m) * E_;
        float addf = (m == wi) ? wmask : 0.f;
        float acc = 0.f;
#pragma unroll
        for (int h = 0; h < 2; h++) {
            int e = lane * 4 + h * 128;
            float4 mv = *reinterpret_cast<const float4*>(mp + e);
            float4 av = *reinterpret_cast<const float4*>(sa + e);
            acc += mv.x * av.x + mv.y * av.y + mv.z * av.z + mv.w * av.w;
            float4 ov;
            ov.x = mv.x + addf * av.x; ov.y = mv.y + addf * av.y;
            ov.z = mv.z + addf * av.z; ov.w = mv.w + addf * av.w;
            *reinterpret_cast<float4*>(mo + e) = ov;
        }
#pragma unroll
        for (int o = 16; o > 0; o >>= 1) acc += __shfl_xor_sync(0xFFFFFFFFu, acc, o);
        if (lane == 0) {
            const float* ofp = of + ((long)b * M_ + m) * F_;
            acc += ofp[0] * swof[0] + ofp[1] * swof[1] + ofp[2] * swof[2] + ofp[3] * swof[3];
            logits[b * M_ + m] = acc;
        }
    }
}

// ---------------- launch ----------------
extern "C" void kernel_launch(void* const* d_in, const int* in_sizes, int n_in,
                              void* d_out, int out_size) {
    const float* memory = (const float*)d_in[0];
    const float* h0     = (const float*)d_in[1];
    const float* c0     = (const float*)d_in[2];
    const float* h1     = (const float*)d_in[3];
    const float* c1     = (const float*)d_in[4];
    const float* keys   = (const float*)d_in[5];
    const float* values = (const float*)d_in[6];
    const float* qmask  = (const float*)d_in[7];
    const float* of     = (const float*)d_in[8];
    const float* W_ih0  = (const float*)d_in[9];
    const float* W_hh0  = (const float*)d_in[10];
    const float* b_ih0  = (const float*)d_in[11];
    const float* b_hh0  = (const float*)d_in[12];
    const float* W_ih1  = (const float*)d_in[13];
    const float* W_hh1  = (const float*)d_in[14];
    const float* b_ih1  = (const float*)d_in[15];
    const float* b_hh1  = (const float*)d_in[16];
    const float* W_att  = (const float*)d_in[17];
    const float* W_of   = (const float*)d_in[18];
    const int* read_ind  = (const int*)d_in[19];
    const int* write_ind = (const int*)d_in[20];
    (void)in_sizes; (void)n_in; (void)out_size;

    float* out = (float*)d_out;
    float* logits   = out;
    float* memory_t = out + (long)B_ * M_;
    float* h0n = memory_t + (long)B_ * M_ * E_;
    float* c0n = h0n + B_ * H_;
    float* h1n = c0n + B_ * H_;
    float* c1n = h1n + B_ * H_;

    static float *pX0f = nullptr, *pX1f, *pXAf, *pW0f, *pW1f, *pG0, *pG1, *pATT;
    static __nv_bfloat16 *pX0hi, *pX0lo, *pX1hi, *pX1lo, *pXAhi, *pXAlo,
                         *pW0hi, *pW0lo, *pW1hi, *pW1lo, *pWAhi, *pWAlo;
    if (!pX0f) {
        cudaGetSymbolAddress((void**)&pX0f, g_X0f);
        cudaGetSymbolAddress((void**)&pX1f, g_X1f);
        cudaGetSymbolAddress((void**)&pXAf, g_XAf);
        cudaGetSymbolAddress((void**)&pW0f, g_W0f);
        cudaGetSymbolAddress((void**)&pW1f, g_W1f);
        cudaGetSymbolAddress((void**)&pG0, g_G0);
        cudaGetSymbolAddress((void**)&pG1, g_G1);
        cudaGetSymbolAddress((void**)&pATT, g_ATT);
        cudaGetSymbolAddress((void**)&pX0hi, g_X0hi);
        cudaGetSymbolAddress((void**)&pX0lo, g_X0lo);
        cudaGetSymbolAddress((void**)&pX1hi, g_X1hi);
        cudaGetSymbolAddress((void**)&pX1lo, g_X1lo);
        cudaGetSymbolAddress((void**)&pXAhi, g_XAhi);
        cudaGetSymbolAddress((void**)&pXAlo, g_XAlo);
        cudaGetSymbolAddress((void**)&pW0hi, g_W0hi);
        cudaGetSymbolAddress((void**)&pW0lo, g_W0lo);
        cudaGetSymbolAddress((void**)&pW1hi, g_W1hi);
        cudaGetSymbolAddress((void**)&pW1lo, g_W1lo);
        cudaGetSymbolAddress((void**)&pWAhi, g_WAhi);
        cudaGetSymbolAddress((void**)&pWAlo, g_WAlo);
        cudaFuncSetAttribute(gemm_uni, cudaFuncAttributeMaxDynamicSharedMemorySize, GEMM_DYN);
    }

    convw_kernel<<<2304, 256>>>(W_ih0, W_hh0, W_ih1, W_hh1, W_att);
    gather0_kernel<<<B_, 256>>>(memory, h0, read_ind);

    gemm_uni<<<dim3(16, 8), 256, GEMM_DYN>>>(pX0f, pX0hi, pX0lo, pW0f, pW0hi, pW0lo,
                                             pG0, 1024, 0);
    cell0_kernel<<<B_, 256>>>(b_ih0, b_hh0, c0, h1, h0n, c0n);

    gemm_uni<<<dim3(16, 8), 256, GEMM_DYN>>>(pX1f, pX1hi, pX1lo, pW1f, pW1hi, pW1lo,
                                             pG1, 1024, 0);
    cellattn_kernel<<<B_, 256>>>(b_ih1, b_hh1, c1, h0n, keys, values, qmask, h1n, c1n);

    gemm_uni<<<dim3(16, 2), 256, GEMM_DYN>>>(pXAf, pXAhi, pXAlo, W_att, pWAhi, pWAlo,
                                             pATT, 256, 1);

    final_kernel<<<B_, 256>>>(memory, of, W_of, write_ind, logits, memory_t);
}